// round 2
// baseline (speedup 1.0000x reference)
#include <cuda_runtime.h>

// Problem constants
#define T_TOKENS 16384
#define D_MODEL  2048
#define N_EXP    8
// top-2 routing

// GEMM tiling
#define BM 128
#define BN 128
#define BK 16
#define SPAD 132   // padded smem row stride (floats); 132*4=528 bytes, 16B-aligned

// Routing scratch (device globals: no allocation allowed in kernel_launch)
__device__ int g_cnt[N_EXP];
__device__ int g_list[N_EXP][T_TOKENS];

// ---------------------------------------------------------------------------
// Kernel 0: zero output + expert counters
// ---------------------------------------------------------------------------
__global__ void moe_zero_kernel(float* __restrict__ out) {
    const long long n4 = (long long)T_TOKENS * D_MODEL / 4;
    long long idx = (long long)blockIdx.x * blockDim.x + threadIdx.x;
    float4 z = make_float4(0.f, 0.f, 0.f, 0.f);
    for (long long i = idx; i < n4; i += (long long)gridDim.x * blockDim.x)
        reinterpret_cast<float4*>(out)[i] = z;
    if (blockIdx.x == 0 && threadIdx.x < N_EXP) g_cnt[threadIdx.x] = 0;
}

// ---------------------------------------------------------------------------
// Kernel 1: router — logits = h @ Wg^T + bg, top-2, gather token ids per expert
// One block (256 threads) per token. Warp w computes logit for expert w.
// ---------------------------------------------------------------------------
__global__ void moe_router_kernel(const float* __restrict__ h,
                                  const float* __restrict__ Wg,
                                  const float* __restrict__ bg) {
    __shared__ float sh[D_MODEL];
    __shared__ float slog[N_EXP];
    const int t = blockIdx.x;
    const float* hr = h + (long long)t * D_MODEL;

    // cooperative row load (256 threads * 8 floats)
    for (int i = threadIdx.x * 4; i < D_MODEL; i += blockDim.x * 4)
        *reinterpret_cast<float4*>(sh + i) = *reinterpret_cast<const float4*>(hr + i);
    __syncthreads();

    const int w = threadIdx.x >> 5;
    const int lane = threadIdx.x & 31;
    const float* wg = Wg + w * D_MODEL;
    float s = 0.f;
    #pragma unroll 4
    for (int i = lane; i < D_MODEL; i += 32) s += sh[i] * wg[i];
    #pragma unroll
    for (int o = 16; o > 0; o >>= 1) s += __shfl_xor_sync(0xffffffffu, s, o);
    if (lane == 0) slog[w] = s + bg[w];
    __syncthreads();

    if (threadIdx.x == 0) {
        // top-1 (lowest index on ties, matching lax.top_k)
        int b0 = 0; float v0 = slog[0];
        #pragma unroll
        for (int i = 1; i < N_EXP; i++) { if (slog[i] > v0) { v0 = slog[i]; b0 = i; } }
        // top-2 among the rest
        int b1 = -1; float v1 = -3.402823466e38f;
        #pragma unroll
        for (int i = 0; i < N_EXP; i++) {
            if (i != b0 && slog[i] > v1) { v1 = slog[i]; b1 = i; }
        }
        int p0 = atomicAdd(&g_cnt[b0], 1); g_list[b0][p0] = t;
        int p1 = atomicAdd(&g_cnt[b1], 1); g_list[b1][p1] = t;
    }
}

// ---------------------------------------------------------------------------
// Kernel 2: grouped GEMM over gathered rows.
// grid.x = ntile (16), grid.y = expert_tile (8 experts * 128 max M-tiles).
// Block computes a [128 x 128] tile of (gathered_h @ W[e]^T + b[e]) and
// atomicAdd's it into out (each token receives exactly 2 expert contributions).
// Classic SIMT fp32 GEMM: 256 threads, 8x8 accumulators per thread.
// ---------------------------------------------------------------------------
__global__ __launch_bounds__(256, 2)
void moe_gemm_kernel(const float* __restrict__ h,
                     const float* __restrict__ W,
                     const float* __restrict__ b,
                     float* __restrict__ out) {
    const int ntile = blockIdx.x;        // 0..15
    const int et    = blockIdx.y;        // 0..1023
    const int e     = et >> 7;           // expert
    const int mtile = et & 127;
    const int cnt   = g_cnt[e];
    const int m0    = mtile * BM;
    if (m0 >= cnt) return;
    const int rows = min(BM, cnt - m0);

    __shared__ float As[BK][SPAD];
    __shared__ float Bs[BK][SPAD];
    __shared__ int rowid[BM];

    const int tid = threadIdx.x;
    if (tid < BM) rowid[tid] = (tid < rows) ? g_list[e][m0 + tid] : -1;
    __syncthreads();

    // W[e] slice for this ntile: rows [ntile*BN, ntile*BN+BN) of W[e] (row = out dim, K contiguous)
    const float* We = W + (long long)e * D_MODEL * D_MODEL + (long long)ntile * BN * D_MODEL;

    float acc[8][8];
    #pragma unroll
    for (int i = 0; i < 8; i++)
        #pragma unroll
        for (int j = 0; j < 8; j++) acc[i][j] = 0.f;

    const int tx = tid & 15;   // output col group
    const int ty = tid >> 4;   // output row group

    // Stage loaders: 512 float4 per operand per k-chunk; thread handles f=tid, f=tid+256.
    const int fm = tid >> 2;           // row within half (0..63)
    const int fc = (tid & 3) * 4;      // k offset within chunk (0,4,8,12)

    for (int k0 = 0; k0 < D_MODEL; k0 += BK) {
        #pragma unroll
        for (int half = 0; half < 2; half++) {
            const int m = fm + half * 64;
            // A (gathered hidden rows)
            const int r = rowid[m];
            float4 v = make_float4(0.f, 0.f, 0.f, 0.f);
            if (r >= 0)
                v = *reinterpret_cast<const float4*>(h + (long long)r * D_MODEL + k0 + fc);
            As[fc + 0][m] = v.x;
            As[fc + 1][m] = v.y;
            As[fc + 2][m] = v.z;
            As[fc + 3][m] = v.w;
            // B (W[e] rows for this ntile)
            float4 u = *reinterpret_cast<const float4*>(We + (long long)m * D_MODEL + k0 + fc);
            Bs[fc + 0][m] = u.x;
            Bs[fc + 1][m] = u.y;
            Bs[fc + 2][m] = u.z;
            Bs[fc + 3][m] = u.w;
        }
        __syncthreads();

        #pragma unroll
        for (int k = 0; k < BK; k++) {
            float a[8], bb[8];
            *reinterpret_cast<float4*>(a)      = *reinterpret_cast<const float4*>(&As[k][ty * 8]);
            *reinterpret_cast<float4*>(a + 4)  = *reinterpret_cast<const float4*>(&As[k][ty * 8 + 4]);
            *reinterpret_cast<float4*>(bb)     = *reinterpret_cast<const float4*>(&Bs[k][tx * 8]);
            *reinterpret_cast<float4*>(bb + 4) = *reinterpret_cast<const float4*>(&Bs[k][tx * 8 + 4]);
            #pragma unroll
            for (int i = 0; i < 8; i++)
                #pragma unroll
                for (int j = 0; j < 8; j++)
                    acc[i][j] += a[i] * bb[j];
        }
        __syncthreads();
    }

    // Epilogue: + bias, atomicAdd into out
    const int nbase = ntile * BN + tx * 8;
    float bias[8];
    #pragma unroll
    for (int j = 0; j < 8; j++) bias[j] = b[e * D_MODEL + nbase + j];

    #pragma unroll
    for (int i = 0; i < 8; i++) {
        const int m = ty * 8 + i;
        const int r = rowid[m];
        if (r < 0) continue;
        float* orow = out + (long long)r * D_MODEL + nbase;
        #pragma unroll
        for (int j = 0; j < 8; j++)
            atomicAdd(orow + j, acc[i][j] + bias[j]);
    }
}

// ---------------------------------------------------------------------------
// Launch
// ---------------------------------------------------------------------------
extern "C" void kernel_launch(void* const* d_in, const int* in_sizes, int n_in,
                              void* d_out, int out_size) {
    const float* h  = (const float*)d_in[0];  // [16384, 2048]
    const float* Wg = (const float*)d_in[1];  // [8, 2048]
    const float* bg = (const float*)d_in[2];  // [8]
    const float* W  = (const float*)d_in[3];  // [8, 2048, 2048]
    const float* b  = (const float*)d_in[4];  // [8, 2048]
    float* out = (float*)d_out;               // [16384, 2048]

    (void)in_sizes; (void)n_in; (void)out_size;

    moe_zero_kernel<<<1024, 256>>>(out);
    moe_router_kernel<<<T_TOKENS, 256>>>(h, Wg, bg);
    dim3 grid(16, N_EXP * (T_TOKENS / BM));  // (ntile, expert*mtile) with early exit
    moe_gemm_kernel<<<grid, 256>>>(h, W, b, out);
}

// round 7
// speedup vs baseline: 2.4001x; 2.4001x over previous
#include <cuda_runtime.h>
#include <cuda_bf16.h>
#include <cstdint>
#include <cstddef>

#define T_TOKENS 16384
#define D_MODEL  2048
#define N_EXP    8

// GEMM tiling
#define BM 128
#define BN 128
#define KC 64                        // bf16 elems per staged K-chunk
#define NCHUNK (D_MODEL / KC)        // 32
#define NT (D_MODEL / BN)            // 16 n-tiles

// Staged row: 72 bf16 = 144 B (64 data + 8 pad) -> conflict-free ldmatrix
#define STRIDE_B 144
#define AH_OFF 0
#define AL_OFF 18432
#define BH_OFF 36864
#define BL_OFF 55296
#define STAGE_BYTES 73728
#define TILES_OFF 1024
#define SMEM_TOTAL (TILES_OFF + 2 * STAGE_BYTES)   // 148480

// ---------------- device scratch ---------------------------------------------
__device__ int g_cnt[N_EXP];
__device__ int g_list[N_EXP][T_TOKENS];                       // packed token*2+slot
__device__ __nv_bfloat16 g_hh[(size_t)T_TOKENS * D_MODEL];
__device__ __nv_bfloat16 g_hl[(size_t)T_TOKENS * D_MODEL];
__device__ __nv_bfloat16 g_wh[(size_t)N_EXP * D_MODEL * D_MODEL];
__device__ __nv_bfloat16 g_wl[(size_t)N_EXP * D_MODEL * D_MODEL];
__device__ float g_scr1[(size_t)T_TOKENS * D_MODEL];          // slot-1 outputs

// ---------------- helpers -----------------------------------------------------
__device__ __forceinline__ uint32_t smem_u32(const void* p) {
    uint32_t a;
    asm("{ .reg .u64 t; cvta.to.shared.u64 t, %1; cvt.u32.u64 %0, t; }" : "=r"(a) : "l"(p));
    return a;
}
__device__ __forceinline__ void cp16(uint32_t dst, const void* src, int sz) {
    asm volatile("cp.async.cg.shared.global [%0], [%1], 16, %2;"
                 :: "r"(dst), "l"(src), "r"(sz) : "memory");
}
__device__ __forceinline__ void cp_commit() {
    asm volatile("cp.async.commit_group;" ::: "memory");
}
__device__ __forceinline__ void ldsm4(uint32_t* r, uint32_t addr) {
    asm volatile("ldmatrix.sync.aligned.m8n8.x4.shared.b16 {%0,%1,%2,%3}, [%4];"
                 : "=r"(r[0]), "=r"(r[1]), "=r"(r[2]), "=r"(r[3]) : "r"(addr));
}
__device__ __forceinline__ void mma16816(float* d, const uint32_t* a, const uint32_t* b) {
    asm volatile(
        "mma.sync.aligned.m16n8k16.row.col.f32.bf16.bf16.f32 "
        "{%0,%1,%2,%3}, {%4,%5,%6,%7}, {%8,%9}, {%0,%1,%2,%3};"
        : "+f"(d[0]), "+f"(d[1]), "+f"(d[2]), "+f"(d[3])
        : "r"(a[0]), "r"(a[1]), "r"(a[2]), "r"(a[3]), "r"(b[0]), "r"(b[1]));
}

// ---------------- kernel: zero routing counters -------------------------------
__global__ void init_kernel() {
    if (threadIdx.x < N_EXP) g_cnt[threadIdx.x] = 0;
}

// ---------------- kernel: fp32 -> (bf16 hi, bf16 lo) --------------------------
__global__ void convert_kernel(const float* __restrict__ src,
                               __nv_bfloat16* __restrict__ hi,
                               __nv_bfloat16* __restrict__ lo, long long n4) {
    long long i = (long long)blockIdx.x * blockDim.x + threadIdx.x;
    for (; i < n4; i += (long long)gridDim.x * blockDim.x) {
        float4 v = reinterpret_cast<const float4*>(src)[i];
        __nv_bfloat16 h0 = __float2bfloat16(v.x);
        __nv_bfloat16 h1 = __float2bfloat16(v.y);
        __nv_bfloat16 h2 = __float2bfloat16(v.z);
        __nv_bfloat16 h3 = __float2bfloat16(v.w);
        __nv_bfloat16 l0 = __float2bfloat16(v.x - __bfloat162float(h0));
        __nv_bfloat16 l1 = __float2bfloat16(v.y - __bfloat162float(h1));
        __nv_bfloat16 l2 = __float2bfloat16(v.z - __bfloat162float(h2));
        __nv_bfloat16 l3 = __float2bfloat16(v.w - __bfloat162float(h3));
        reinterpret_cast<__nv_bfloat162*>(hi)[i * 2 + 0] = __nv_bfloat162(h0, h1);
        reinterpret_cast<__nv_bfloat162*>(hi)[i * 2 + 1] = __nv_bfloat162(h2, h3);
        reinterpret_cast<__nv_bfloat162*>(lo)[i * 2 + 0] = __nv_bfloat162(l0, l1);
        reinterpret_cast<__nv_bfloat162*>(lo)[i * 2 + 1] = __nv_bfloat162(l2, l3);
    }
}

// ---------------- kernel: router (4 tokens / block) ---------------------------
__global__ __launch_bounds__(256) void router_kernel(const float* __restrict__ h,
                                                     const float* __restrict__ Wg,
                                                     const float* __restrict__ bg) {
    __shared__ float sh[4][D_MODEL];
    __shared__ float slog[4][N_EXP];
    const int tid = threadIdx.x;
    const int t0 = blockIdx.x * 4;

    for (int i = tid * 4; i < 4 * D_MODEL; i += 256 * 4)
        *reinterpret_cast<float4*>(&sh[0][0] + i) =
            *reinterpret_cast<const float4*>(h + (size_t)t0 * D_MODEL + i);

    const int w = tid >> 5, lane = tid & 31;
    float wreg[64];
    #pragma unroll
    for (int j = 0; j < 64; j++) wreg[j] = Wg[w * D_MODEL + lane + j * 32];
    __syncthreads();

    #pragma unroll
    for (int tk = 0; tk < 4; tk++) {
        float s = 0.f;
        #pragma unroll
        for (int j = 0; j < 64; j++) s += sh[tk][lane + j * 32] * wreg[j];
        #pragma unroll
        for (int o = 16; o > 0; o >>= 1) s += __shfl_xor_sync(0xffffffffu, s, o);
        if (lane == 0) slog[tk][w] = s + bg[w];
    }
    __syncthreads();

    if (tid < 4) {
        const int token = t0 + tid;
        int b0 = 0; float v0 = slog[tid][0];
        #pragma unroll
        for (int i = 1; i < N_EXP; i++) if (slog[tid][i] > v0) { v0 = slog[tid][i]; b0 = i; }
        int b1 = -1; float v1 = -3.402823466e38f;
        #pragma unroll
        for (int i = 0; i < N_EXP; i++)
            if (i != b0 && slog[tid][i] > v1) { v1 = slog[tid][i]; b1 = i; }
        int p0 = atomicAdd(&g_cnt[b0], 1); g_list[b0][p0] = token * 2;       // -> out
        int p1 = atomicAdd(&g_cnt[b1], 1); g_list[b1][p1] = token * 2 + 1;   // -> scr1
    }
}

// ---------------- kernel: grouped GEMM via mma.sync bf16 (hi/lo split) --------
// grid.x = ntile (16), grid.y = e*128 + mtile. 256 threads = 8 warps (4m x 2n).
// Warp tile 32x64, fragments m16n8k16. acc fp32. A rows gathered via rowid.
__global__ __launch_bounds__(256, 1)
void moe_mma_gemm(const float* __restrict__ bias, float* __restrict__ out) {
    extern __shared__ char smem[];
    const uint32_t sb = smem_u32(smem);
    int* rowid = reinterpret_cast<int*>(smem);
    const int tid = threadIdx.x;
    const int ntile = blockIdx.x;
    const int et = blockIdx.y;
    const int e = et >> 7;
    const int mtile = et & 127;
    const int cnt = g_cnt[e];
    const int m0 = mtile * BM;
    if (m0 >= cnt) return;

    if (tid < BM) rowid[tid] = (m0 + tid < cnt) ? g_list[e][m0 + tid] : -1;
    __syncthreads();

    const __nv_bfloat16* Whb = g_wh + ((size_t)e * D_MODEL + (size_t)ntile * BN) * D_MODEL;
    const __nv_bfloat16* Wlb = g_wl + ((size_t)e * D_MODEL + (size_t)ntile * BN) * D_MODEL;

    // ---- staging (cp.async): 4 matrices x 1024 16B-chunks, 16 per thread ----
    auto stage_load = [&](int st, int c) {
        const int k0 = c * KC;
        const uint32_t base = sb + TILES_OFF + st * STAGE_BYTES;
        #pragma unroll
        for (int i = 0; i < 4; i++) {
            const int u = tid + i * 256;          // 0..1023
            const int row = u >> 3, cc = u & 7;
            const uint32_t d = base + row * STRIDE_B + cc * 16;
            const int sv = rowid[row];
            const int sz = (sv >= 0) ? 16 : 0;
            const size_t aoff = (size_t)((sv >= 0) ? (sv >> 1) : 0) * D_MODEL + k0 + cc * 8;
            cp16(d + AH_OFF, g_hh + aoff, sz);
            cp16(d + AL_OFF, g_hl + aoff, sz);
            const size_t boff = (size_t)row * D_MODEL + k0 + cc * 8;
            cp16(d + BH_OFF, Whb + boff, 16);
            cp16(d + BL_OFF, Wlb + boff, 16);
        }
        cp_commit();
    };

    const int lane = tid & 31, wid = tid >> 5;
    const int wm = wid & 3;                     // 4 warps over 128 rows
    const int wn = wid >> 2;                    // 2 warps over 128 cols
    const uint32_t arow = (uint32_t)((wm * 32 + (lane & 15)) * STRIDE_B + (lane >> 4) * 16);
    const uint32_t brow = (uint32_t)((wn * 64 + (lane & 15)) * STRIDE_B + (lane >> 4) * 16);

    float acc[2][8][4];
    #pragma unroll
    for (int mf = 0; mf < 2; mf++)
        #pragma unroll
        for (int n8 = 0; n8 < 8; n8++)
            #pragma unroll
            for (int q = 0; q < 4; q++) acc[mf][n8][q] = 0.f;

    stage_load(0, 0);

    for (int c = 0; c < NCHUNK; c++) {
        if (c + 1 < NCHUNK) {
            stage_load((c + 1) & 1, c + 1);
            asm volatile("cp.async.wait_group 1;" ::: "memory");
        } else {
            asm volatile("cp.async.wait_group 0;" ::: "memory");
        }
        __syncthreads();

        const uint32_t stb = sb + TILES_OFF + (c & 1) * STAGE_BYTES;
        #pragma unroll
        for (int ks = 0; ks < 4; ks++) {
            const uint32_t koff = ks * 32;      // 16 bf16 = 32 B
            uint32_t ah[2][4], al[2][4];
            #pragma unroll
            for (int mf = 0; mf < 2; mf++) {
                ldsm4(ah[mf], stb + AH_OFF + arow + mf * (16 * STRIDE_B) + koff);
                ldsm4(al[mf], stb + AL_OFF + arow + mf * (16 * STRIDE_B) + koff);
            }
            uint32_t bh[8][2], bl[8][2];
            #pragma unroll
            for (int nf = 0; nf < 4; nf++) {
                uint32_t r[4];
                ldsm4(r, stb + BH_OFF + brow + nf * (16 * STRIDE_B) + koff);
                bh[nf * 2 + 0][0] = r[0]; bh[nf * 2 + 0][1] = r[2];
                bh[nf * 2 + 1][0] = r[1]; bh[nf * 2 + 1][1] = r[3];
                ldsm4(r, stb + BL_OFF + brow + nf * (16 * STRIDE_B) + koff);
                bl[nf * 2 + 0][0] = r[0]; bl[nf * 2 + 0][1] = r[2];
                bl[nf * 2 + 1][0] = r[1]; bl[nf * 2 + 1][1] = r[3];
            }
            #pragma unroll
            for (int mf = 0; mf < 2; mf++)
                #pragma unroll
                for (int n8 = 0; n8 < 8; n8++) {
                    mma16816(acc[mf][n8], ah[mf], bh[n8]);
                    mma16816(acc[mf][n8], al[mf], bh[n8]);
                    mma16816(acc[mf][n8], ah[mf], bl[n8]);
                }
        }
        __syncthreads();
    }

    // ---- epilogue: + bias, scatter rows to out (slot 0) / scr1 (slot 1) ----
    const int quad = lane >> 2, tq = lane & 3;
    #pragma unroll
    for (int mf = 0; mf < 2; mf++) {
        #pragma unroll
        for (int half = 0; half < 2; half++) {
            const int mrow = wm * 32 + mf * 16 + half * 8 + quad;
            const int sv = rowid[mrow];
            if (sv < 0) continue;
            float* dst = ((sv & 1) ? g_scr1 : out) + (size_t)(sv >> 1) * D_MODEL;
            #pragma unroll
            for (int n8 = 0; n8 < 8; n8++) {
                const int gcol = ntile * BN + wn * 64 + n8 * 8 + tq * 2;
                const float* bp = bias + e * D_MODEL + gcol;
                float2 o;
                o.x = acc[mf][n8][half * 2 + 0] + bp[0];
                o.y = acc[mf][n8][half * 2 + 1] + bp[1];
                *reinterpret_cast<float2*>(dst + gcol) = o;
            }
        }
    }
}

// ---------------- kernel: combine (out[t] += scr1[t]) -------------------------
__global__ void combine_kernel(float* __restrict__ out) {
    const long long n4 = (long long)T_TOKENS * D_MODEL / 4;
    const float4* s4 = reinterpret_cast<const float4*>(g_scr1);
    float4* o4 = reinterpret_cast<float4*>(out);
    for (long long i = (long long)blockIdx.x * blockDim.x + threadIdx.x; i < n4;
         i += (long long)gridDim.x * blockDim.x) {
        float4 a = o4[i];
        float4 b = s4[i];
        o4[i] = make_float4(a.x + b.x, a.y + b.y, a.z + b.z, a.w + b.w);
    }
}

// ---------------- launch ------------------------------------------------------
extern "C" void kernel_launch(void* const* d_in, const int* in_sizes, int n_in,
                              void* d_out, int out_size) {
    const float* h  = (const float*)d_in[0];   // [16384, 2048]
    const float* Wg = (const float*)d_in[1];   // [8, 2048]
    const float* bg = (const float*)d_in[2];   // [8]
    const float* W  = (const float*)d_in[3];   // [8, 2048, 2048]
    const float* b  = (const float*)d_in[4];   // [8, 2048]
    float* out = (float*)d_out;                // [16384, 2048]
    (void)in_sizes; (void)n_in; (void)out_size;

    init_kernel<<<1, 32>>>();

    __nv_bfloat16 *hh, *hl, *wh, *wl;
    cudaGetSymbolAddress((void**)&hh, g_hh);
    cudaGetSymbolAddress((void**)&hl, g_hl);
    cudaGetSymbolAddress((void**)&wh, g_wh);
    cudaGetSymbolAddress((void**)&wl, g_wl);

    convert_kernel<<<4096, 256>>>(h, hh, hl, (long long)T_TOKENS * D_MODEL / 4);
    convert_kernel<<<8192, 256>>>(W, wh, wl, (long long)N_EXP * D_MODEL * D_MODEL / 4);
    router_kernel<<<T_TOKENS / 4, 256>>>(h, Wg, bg);

    cudaFuncSetAttribute(moe_mma_gemm, cudaFuncAttributeMaxDynamicSharedMemorySize, SMEM_TOTAL);
    dim3 grid(NT, N_EXP * (T_TOKENS / BM));
    moe_mma_gemm<<<grid, 256, SMEM_TOTAL>>>(b, out);

    combine_kernel<<<1024, 256>>>(out);
}

// round 10
// speedup vs baseline: 2.5506x; 1.0627x over previous
#include <cuda_runtime.h>
#include <cuda_bf16.h>
#include <cstdint>
#include <cstddef>

#define T_TOKENS 16384
#define D_MODEL  2048
#define N_EXP    8

// GEMM tiling
#define BM 128
#define BN 128
#define KC 32                        // bf16 elems per staged K-chunk
#define NCHUNK (D_MODEL / KC)        // 64
#define NT (D_MODEL / BN)            // 16 n-tiles

// Staged row: 40 bf16 = 80 B (32 data + 8 pad) -> conflict-free ldmatrix
// (row offsets mod 32 words: 0,20,8,28,16,4,24,12 -> disjoint 4-word quads)
#define STRIDE_B 80
#define AH_OFF 0
#define AL_OFF 10240
#define BH_OFF 20480
#define BL_OFF 30720
#define STAGE_BYTES 40960
#define TILES_OFF 1024
#define SMEM_TOTAL (TILES_OFF + 2 * STAGE_BYTES)   // 82944 -> 2 CTAs/SM

// ---------------- device scratch ---------------------------------------------
__device__ int g_cnt[N_EXP];
__device__ int g_list[N_EXP][T_TOKENS];                       // packed token*2+slot
__device__ __nv_bfloat16 g_hh[(size_t)T_TOKENS * D_MODEL];
__device__ __nv_bfloat16 g_hl[(size_t)T_TOKENS * D_MODEL];
__device__ __nv_bfloat16 g_wh[(size_t)N_EXP * D_MODEL * D_MODEL];
__device__ __nv_bfloat16 g_wl[(size_t)N_EXP * D_MODEL * D_MODEL];
__device__ float g_scr1[(size_t)T_TOKENS * D_MODEL];          // slot-1 outputs

// ---------------- helpers -----------------------------------------------------
__device__ __forceinline__ uint32_t smem_u32(const void* p) {
    uint32_t a;
    asm("{ .reg .u64 t; cvta.to.shared.u64 t, %1; cvt.u32.u64 %0, t; }" : "=r"(a) : "l"(p));
    return a;
}
__device__ __forceinline__ void cp16(uint32_t dst, const void* src, int sz) {
    asm volatile("cp.async.cg.shared.global [%0], [%1], 16, %2;"
                 :: "r"(dst), "l"(src), "r"(sz) : "memory");
}
__device__ __forceinline__ void cp_commit() {
    asm volatile("cp.async.commit_group;" ::: "memory");
}
__device__ __forceinline__ void ldsm4(uint32_t* r, uint32_t addr) {
    asm volatile("ldmatrix.sync.aligned.m8n8.x4.shared.b16 {%0,%1,%2,%3}, [%4];"
                 : "=r"(r[0]), "=r"(r[1]), "=r"(r[2]), "=r"(r[3]) : "r"(addr));
}
__device__ __forceinline__ void mma16816(float* d, const uint32_t* a, const uint32_t* b) {
    asm volatile(
        "mma.sync.aligned.m16n8k16.row.col.f32.bf16.bf16.f32 "
        "{%0,%1,%2,%3}, {%4,%5,%6,%7}, {%8,%9}, {%0,%1,%2,%3};"
        : "+f"(d[0]), "+f"(d[1]), "+f"(d[2]), "+f"(d[3])
        : "r"(a[0]), "r"(a[1]), "r"(a[2]), "r"(a[3]), "r"(b[0]), "r"(b[1]));
}

// ---------------- kernel: zero routing counters -------------------------------
__global__ void init_kernel() {
    if (threadIdx.x < N_EXP) g_cnt[threadIdx.x] = 0;
}

// ---------------- kernel: fp32 -> (bf16 hi, bf16 lo) --------------------------
__global__ void convert_kernel(const float* __restrict__ src,
                               __nv_bfloat16* __restrict__ hi,
                               __nv_bfloat16* __restrict__ lo, long long n4) {
    long long i = (long long)blockIdx.x * blockDim.x + threadIdx.x;
    for (; i < n4; i += (long long)gridDim.x * blockDim.x) {
        float4 v = reinterpret_cast<const float4*>(src)[i];
        __nv_bfloat16 h0 = __float2bfloat16(v.x);
        __nv_bfloat16 h1 = __float2bfloat16(v.y);
        __nv_bfloat16 h2 = __float2bfloat16(v.z);
        __nv_bfloat16 h3 = __float2bfloat16(v.w);
        __nv_bfloat16 l0 = __float2bfloat16(v.x - __bfloat162float(h0));
        __nv_bfloat16 l1 = __float2bfloat16(v.y - __bfloat162float(h1));
        __nv_bfloat16 l2 = __float2bfloat16(v.z - __bfloat162float(h2));
        __nv_bfloat16 l3 = __float2bfloat16(v.w - __bfloat162float(h3));
        reinterpret_cast<__nv_bfloat162*>(hi)[i * 2 + 0] = __nv_bfloat162(h0, h1);
        reinterpret_cast<__nv_bfloat162*>(hi)[i * 2 + 1] = __nv_bfloat162(h2, h3);
        reinterpret_cast<__nv_bfloat162*>(lo)[i * 2 + 0] = __nv_bfloat162(l0, l1);
        reinterpret_cast<__nv_bfloat162*>(lo)[i * 2 + 1] = __nv_bfloat162(l2, l3);
    }
}

// ---------------- kernel: router (4 tokens / block) ---------------------------
__global__ __launch_bounds__(256) void router_kernel(const float* __restrict__ h,
                                                     const float* __restrict__ Wg,
                                                     const float* __restrict__ bg) {
    __shared__ float sh[4][D_MODEL];
    __shared__ float slog[4][N_EXP];
    const int tid = threadIdx.x;
    const int t0 = blockIdx.x * 4;

    for (int i = tid * 4; i < 4 * D_MODEL; i += 256 * 4)
        *reinterpret_cast<float4*>(&sh[0][0] + i) =
            *reinterpret_cast<const float4*>(h + (size_t)t0 * D_MODEL + i);

    const int w = tid >> 5, lane = tid & 31;
    float wreg[64];
    #pragma unroll
    for (int j = 0; j < 64; j++) wreg[j] = Wg[w * D_MODEL + lane + j * 32];
    __syncthreads();

    #pragma unroll
    for (int tk = 0; tk < 4; tk++) {
        float s = 0.f;
        #pragma unroll
        for (int j = 0; j < 64; j++) s += sh[tk][lane + j * 32] * wreg[j];
        #pragma unroll
        for (int o = 16; o > 0; o >>= 1) s += __shfl_xor_sync(0xffffffffu, s, o);
        if (lane == 0) slog[tk][w] = s + bg[w];
    }
    __syncthreads();

    if (tid < 4) {
        const int token = t0 + tid;
        int b0 = 0; float v0 = slog[tid][0];
        #pragma unroll
        for (int i = 1; i < N_EXP; i++) if (slog[tid][i] > v0) { v0 = slog[tid][i]; b0 = i; }
        int b1 = -1; float v1 = -3.402823466e38f;
        #pragma unroll
        for (int i = 0; i < N_EXP; i++)
            if (i != b0 && slog[tid][i] > v1) { v1 = slog[tid][i]; b1 = i; }
        int p0 = atomicAdd(&g_cnt[b0], 1); g_list[b0][p0] = token * 2;       // -> out
        int p1 = atomicAdd(&g_cnt[b1], 1); g_list[b1][p1] = token * 2 + 1;   // -> scr1
    }
}

// ---------------- kernel: grouped GEMM via mma.sync bf16 (hi/lo split) --------
// grid.x = ntile (16), grid.y = e*128 + mtile. 256 threads = 8 warps (4m x 2n).
// Warp tile 32x64, fragments m16n8k16, fp32 acc. 2 CTAs/SM (81 KB smem each).
__global__ __launch_bounds__(256, 2)
void moe_mma_gemm(const float* __restrict__ bias, float* __restrict__ out) {
    extern __shared__ char smem[];
    const uint32_t sb = smem_u32(smem);
    int* rowid = reinterpret_cast<int*>(smem);
    const int tid = threadIdx.x;
    const int ntile = blockIdx.x;
    const int et = blockIdx.y;
    const int e = et >> 7;
    const int mtile = et & 127;
    const int cnt = g_cnt[e];
    const int m0 = mtile * BM;
    if (m0 >= cnt) return;

    if (tid < BM) rowid[tid] = (m0 + tid < cnt) ? g_list[e][m0 + tid] : -1;
    __syncthreads();

    const __nv_bfloat16* Whb = g_wh + ((size_t)e * D_MODEL + (size_t)ntile * BN) * D_MODEL;
    const __nv_bfloat16* Wlb = g_wl + ((size_t)e * D_MODEL + (size_t)ntile * BN) * D_MODEL;

    // ---- staging: per stage, per matrix 512 16B-chunks (128 rows x 4) ----
    auto stage_load = [&](int st, int c) {
        const int k0 = c * KC;
        const uint32_t base = sb + TILES_OFF + st * STAGE_BYTES;
        #pragma unroll
        for (int i = 0; i < 2; i++) {
            const int u = tid + i * 256;          // 0..511
            const int row = u >> 2, cc = u & 3;
            const uint32_t d = base + row * STRIDE_B + cc * 16;
            const int sv = rowid[row];
            const int sz = (sv >= 0) ? 16 : 0;
            const size_t aoff = (size_t)((sv >= 0) ? (sv >> 1) : 0) * D_MODEL + k0 + cc * 8;
            cp16(d + AH_OFF, g_hh + aoff, sz);
            cp16(d + AL_OFF, g_hl + aoff, sz);
            const size_t boff = (size_t)row * D_MODEL + k0 + cc * 8;
            cp16(d + BH_OFF, Whb + boff, 16);
            cp16(d + BL_OFF, Wlb + boff, 16);
        }
        cp_commit();
    };

    const int lane = tid & 31, wid = tid >> 5;
    const int wm = wid & 3;                     // 4 warps over 128 rows
    const int wn = wid >> 2;                    // 2 warps over 128 cols
    const uint32_t arow = (uint32_t)((wm * 32 + (lane & 15)) * STRIDE_B + (lane >> 4) * 16);
    const uint32_t brow = (uint32_t)((wn * 64 + (lane & 15)) * STRIDE_B + (lane >> 4) * 16);

    float acc[2][8][4];
    #pragma unroll
    for (int mf = 0; mf < 2; mf++)
        #pragma unroll
        for (int n8 = 0; n8 < 8; n8++)
            #pragma unroll
            for (int q = 0; q < 4; q++) acc[mf][n8][q] = 0.f;

    stage_load(0, 0);

    for (int c = 0; c < NCHUNK; c++) {
        if (c + 1 < NCHUNK) {
            stage_load((c + 1) & 1, c + 1);
            asm volatile("cp.async.wait_group 1;" ::: "memory");
        } else {
            asm volatile("cp.async.wait_group 0;" ::: "memory");
        }
        __syncthreads();

        const uint32_t stb = sb + TILES_OFF + (c & 1) * STAGE_BYTES;
        #pragma unroll
        for (int ks = 0; ks < 2; ks++) {
            const uint32_t koff = ks * 32;      // 16 bf16 = 32 B
            uint32_t ah[2][4], al[2][4];
            #pragma unroll
            for (int mf = 0; mf < 2; mf++) {
                ldsm4(ah[mf], stb + AH_OFF + arow + mf * (16 * STRIDE_B) + koff);
                ldsm4(al[mf], stb + AL_OFF + arow + mf * (16 * STRIDE_B) + koff);
            }
            uint32_t bh[8][2], bl[8][2];
            #pragma unroll
            for (int nf = 0; nf < 4; nf++) {
                uint32_t r[4];
                ldsm4(r, stb + BH_OFF + brow + nf * (16 * STRIDE_B) + koff);
                bh[nf * 2 + 0][0] = r[0]; bh[nf * 2 + 0][1] = r[2];
                bh[nf * 2 + 1][0] = r[1]; bh[nf * 2 + 1][1] = r[3];
                ldsm4(r, stb + BL_OFF + brow + nf * (16 * STRIDE_B) + koff);
                bl[nf * 2 + 0][0] = r[0]; bl[nf * 2 + 0][1] = r[2];
                bl[nf * 2 + 1][0] = r[1]; bl[nf * 2 + 1][1] = r[3];
            }
            #pragma unroll
            for (int mf = 0; mf < 2; mf++)
                #pragma unroll
                for (int n8 = 0; n8 < 8; n8++) {
                    mma16816(acc[mf][n8], ah[mf], bh[n8]);
                    mma16816(acc[mf][n8], al[mf], bh[n8]);
                    mma16816(acc[mf][n8], ah[mf], bl[n8]);
                }
        }
        __syncthreads();
    }

    // ---- epilogue: + bias, scatter rows to out (slot 0) / scr1 (slot 1) ----
    const int quad = lane >> 2, tq = lane & 3;
    #pragma unroll
    for (int mf = 0; mf < 2; mf++) {
        #pragma unroll
        for (int half = 0; half < 2; half++) {
            const int mrow = wm * 32 + mf * 16 + half * 8 + quad;
            const int sv = rowid[mrow];
            if (sv < 0) continue;
            float* dst = ((sv & 1) ? g_scr1 : out) + (size_t)(sv >> 1) * D_MODEL;
            #pragma unroll
            for (int n8 = 0; n8 < 8; n8++) {
                const int gcol = ntile * BN + wn * 64 + n8 * 8 + tq * 2;
                const float* bp = bias + e * D_MODEL + gcol;
                float2 o;
                o.x = acc[mf][n8][half * 2 + 0] + bp[0];
                o.y = acc[mf][n8][half * 2 + 1] + bp[1];
                *reinterpret_cast<float2*>(dst + gcol) = o;
            }
        }
    }
}

// ---------------- kernel: combine (out[t] += scr1[t]) -------------------------
__global__ void combine_kernel(float* __restrict__ out) {
    const long long n4 = (long long)T_TOKENS * D_MODEL / 4;
    const float4* s4 = reinterpret_cast<const float4*>(g_scr1);
    float4* o4 = reinterpret_cast<float4*>(out);
    for (long long i = (long long)blockIdx.x * blockDim.x + threadIdx.x; i < n4;
         i += (long long)gridDim.x * blockDim.x) {
        float4 a = o4[i];
        float4 b = s4[i];
        o4[i] = make_float4(a.x + b.x, a.y + b.y, a.z + b.z, a.w + b.w);
    }
}

// ---------------- launch ------------------------------------------------------
extern "C" void kernel_launch(void* const* d_in, const int* in_sizes, int n_in,
                              void* d_out, int out_size) {
    const float* h  = (const float*)d_in[0];   // [16384, 2048]
    const float* Wg = (const float*)d_in[1];   // [8, 2048]
    const float* bg = (const float*)d_in[2];   // [8]
    const float* W  = (const float*)d_in[3];   // [8, 2048, 2048]
    const float* b  = (const float*)d_in[4];   // [8, 2048]
    float* out = (float*)d_out;                // [16384, 2048]
    (void)in_sizes; (void)n_in; (void)out_size;

    init_kernel<<<1, 32>>>();

    __nv_bfloat16 *hh, *hl, *wh, *wl;
    cudaGetSymbolAddress((void**)&hh, g_hh);
    cudaGetSymbolAddress((void**)&hl, g_hl);
    cudaGetSymbolAddress((void**)&wh, g_wh);
    cudaGetSymbolAddress((void**)&wl, g_wl);

    convert_kernel<<<4096, 256>>>(h, hh, hl, (long long)T_TOKENS * D_MODEL / 4);
    convert_kernel<<<8192, 256>>>(W, wh, wl, (long long)N_EXP * D_MODEL * D_MODEL / 4);
    router_kernel<<<T_TOKENS / 4, 256>>>(h, Wg, bg);

    cudaFuncSetAttribute(moe_mma_gemm, cudaFuncAttributeMaxDynamicSharedMemorySize, SMEM_TOTAL);
    dim3 grid(NT, N_EXP * (T_TOKENS / BM));
    moe_mma_gemm<<<grid, 256, SMEM_TOTAL>>>(b, out);

    combine_kernel<<<1024, 256>>>(out);
}

// round 11
// speedup vs baseline: 2.5879x; 1.0146x over previous
#include <cuda_runtime.h>
#include <cuda_bf16.h>
#include <cstdint>
#include <cstddef>

#define T_TOKENS 16384
#define D_MODEL  2048
#define N_EXP    8

// GEMM tiling
#define BM 128
#define BN 128
#define KC 32                        // bf16 elems per staged K-chunk
#define NCHUNK (D_MODEL / KC)        // 64
#define NT (D_MODEL / BN)            // 16 n-tiles

// Staged row: 40 bf16 = 80 B (32 data + 8 pad) -> conflict-free ldmatrix
#define STRIDE_B 80
#define AH_OFF 0
#define AL_OFF 10240
#define BH_OFF 20480
#define BL_OFF 30720
#define STAGE_BYTES 40960
#define TILES_OFF 1024
#define SMEM_TOTAL (TILES_OFF + 2 * STAGE_BYTES)   // 82944 -> 2 CTAs/SM

// ---------------- device scratch ---------------------------------------------
__device__ int g_cnt[N_EXP];
__device__ int g_list[N_EXP][T_TOKENS];                       // packed token*2+slot
__device__ __nv_bfloat16 g_hh[(size_t)T_TOKENS * D_MODEL];
__device__ __nv_bfloat16 g_hl[(size_t)T_TOKENS * D_MODEL];
__device__ __nv_bfloat16 g_wh[(size_t)N_EXP * D_MODEL * D_MODEL];
__device__ __nv_bfloat16 g_wl[(size_t)N_EXP * D_MODEL * D_MODEL];
__device__ float g_scr1[(size_t)T_TOKENS * D_MODEL];          // slot-1 outputs

// ---------------- helpers -----------------------------------------------------
__device__ __forceinline__ uint32_t smem_u32(const void* p) {
    uint32_t a;
    asm("{ .reg .u64 t; cvta.to.shared.u64 t, %1; cvt.u32.u64 %0, t; }" : "=r"(a) : "l"(p));
    return a;
}
__device__ __forceinline__ void cp16(uint32_t dst, const void* src, int sz) {
    asm volatile("cp.async.cg.shared.global [%0], [%1], 16, %2;"
                 :: "r"(dst), "l"(src), "r"(sz) : "memory");
}
__device__ __forceinline__ void cp_commit() {
    asm volatile("cp.async.commit_group;" ::: "memory");
}
__device__ __forceinline__ void ldsm4(uint32_t* r, uint32_t addr) {
    asm volatile("ldmatrix.sync.aligned.m8n8.x4.shared.b16 {%0,%1,%2,%3}, [%4];"
                 : "=r"(r[0]), "=r"(r[1]), "=r"(r[2]), "=r"(r[3]) : "r"(addr));
}
__device__ __forceinline__ void mma16816(float* d, const uint32_t* a, const uint32_t* b) {
    asm volatile(
        "mma.sync.aligned.m16n8k16.row.col.f32.bf16.bf16.f32 "
        "{%0,%1,%2,%3}, {%4,%5,%6,%7}, {%8,%9}, {%0,%1,%2,%3};"
        : "+f"(d[0]), "+f"(d[1]), "+f"(d[2]), "+f"(d[3])
        : "r"(a[0]), "r"(a[1]), "r"(a[2]), "r"(a[3]), "r"(b[0]), "r"(b[1]));
}

// ---------------- kernel: zero routing counters -------------------------------
__global__ void init_kernel() {
    if (threadIdx.x < N_EXP) g_cnt[threadIdx.x] = 0;
}

// ---------------- kernel: fused h convert (fp32 -> hi/lo bf16) + router -------
// 4 tokens / block. One DRAM pass over h: rows staged in smem serve both the
// hi/lo split emission and the router dot products.
__global__ __launch_bounds__(256) void prep_kernel(const float* __restrict__ h,
                                                   const float* __restrict__ Wg,
                                                   const float* __restrict__ bg) {
    __shared__ float sh[4 * D_MODEL];      // 32 KB
    __shared__ float slog[4][N_EXP];
    const int tid = threadIdx.x;
    const int t0 = blockIdx.x * 4;
    const size_t base = (size_t)t0 * D_MODEL;

    // stage 4 rows
    for (int i = tid * 4; i < 4 * D_MODEL; i += 256 * 4)
        *reinterpret_cast<float4*>(sh + i) =
            *reinterpret_cast<const float4*>(h + base + i);
    __syncthreads();

    // emit hi/lo bf16 (contiguous 4-row span)
    for (int i = tid * 4; i < 4 * D_MODEL; i += 256 * 4) {
        float4 v = *reinterpret_cast<const float4*>(sh + i);
        __nv_bfloat16 h0 = __float2bfloat16(v.x);
        __nv_bfloat16 h1 = __float2bfloat16(v.y);
        __nv_bfloat16 h2 = __float2bfloat16(v.z);
        __nv_bfloat16 h3 = __float2bfloat16(v.w);
        __nv_bfloat16 l0 = __float2bfloat16(v.x - __bfloat162float(h0));
        __nv_bfloat16 l1 = __float2bfloat16(v.y - __bfloat162float(h1));
        __nv_bfloat16 l2 = __float2bfloat16(v.z - __bfloat162float(h2));
        __nv_bfloat16 l3 = __float2bfloat16(v.w - __bfloat162float(h3));
        *reinterpret_cast<__nv_bfloat162*>(g_hh + base + i)     = __nv_bfloat162(h0, h1);
        *reinterpret_cast<__nv_bfloat162*>(g_hh + base + i + 2) = __nv_bfloat162(h2, h3);
        *reinterpret_cast<__nv_bfloat162*>(g_hl + base + i)     = __nv_bfloat162(l0, l1);
        *reinterpret_cast<__nv_bfloat162*>(g_hl + base + i + 2) = __nv_bfloat162(l2, l3);
    }

    // router: warp w -> expert w logits for the 4 tokens
    const int w = tid >> 5, lane = tid & 31;
    float wreg[64];
    #pragma unroll
    for (int j = 0; j < 64; j++) wreg[j] = Wg[w * D_MODEL + lane + j * 32];

    #pragma unroll
    for (int tk = 0; tk < 4; tk++) {
        float s = 0.f;
        #pragma unroll
        for (int j = 0; j < 64; j++) s += sh[tk * D_MODEL + lane + j * 32] * wreg[j];
        #pragma unroll
        for (int o = 16; o > 0; o >>= 1) s += __shfl_xor_sync(0xffffffffu, s, o);
        if (lane == 0) slog[tk][w] = s + bg[w];
    }
    __syncthreads();

    if (tid < 4) {
        const int token = t0 + tid;
        int b0 = 0; float v0 = slog[tid][0];
        #pragma unroll
        for (int i = 1; i < N_EXP; i++) if (slog[tid][i] > v0) { v0 = slog[tid][i]; b0 = i; }
        int b1 = -1; float v1 = -3.402823466e38f;
        #pragma unroll
        for (int i = 0; i < N_EXP; i++)
            if (i != b0 && slog[tid][i] > v1) { v1 = slog[tid][i]; b1 = i; }
        int p0 = atomicAdd(&g_cnt[b0], 1); g_list[b0][p0] = token * 2;       // -> out
        int p1 = atomicAdd(&g_cnt[b1], 1); g_list[b1][p1] = token * 2 + 1;   // -> scr1
    }
}

// ---------------- kernel: W fp32 -> (bf16 hi, bf16 lo) ------------------------
__global__ void convert_kernel(const float* __restrict__ src,
                               __nv_bfloat16* __restrict__ hi,
                               __nv_bfloat16* __restrict__ lo, long long n4) {
    long long i = (long long)blockIdx.x * blockDim.x + threadIdx.x;
    for (; i < n4; i += (long long)gridDim.x * blockDim.x) {
        float4 v = reinterpret_cast<const float4*>(src)[i];
        __nv_bfloat16 h0 = __float2bfloat16(v.x);
        __nv_bfloat16 h1 = __float2bfloat16(v.y);
        __nv_bfloat16 h2 = __float2bfloat16(v.z);
        __nv_bfloat16 h3 = __float2bfloat16(v.w);
        __nv_bfloat16 l0 = __float2bfloat16(v.x - __bfloat162float(h0));
        __nv_bfloat16 l1 = __float2bfloat16(v.y - __bfloat162float(h1));
        __nv_bfloat16 l2 = __float2bfloat16(v.z - __bfloat162float(h2));
        __nv_bfloat16 l3 = __float2bfloat16(v.w - __bfloat162float(h3));
        reinterpret_cast<__nv_bfloat162*>(hi)[i * 2 + 0] = __nv_bfloat162(h0, h1);
        reinterpret_cast<__nv_bfloat162*>(hi)[i * 2 + 1] = __nv_bfloat162(h2, h3);
        reinterpret_cast<__nv_bfloat162*>(lo)[i * 2 + 0] = __nv_bfloat162(l0, l1);
        reinterpret_cast<__nv_bfloat162*>(lo)[i * 2 + 1] = __nv_bfloat162(l2, l3);
    }
}

// ---------------- kernel: grouped GEMM via mma.sync bf16 (hi/lo split) --------
// grid.x = ntile (16), grid.y = e*128 + mtile. 256 threads = 8 warps (4m x 2n).
// Warp tile 32x64, fragments m16n8k16, fp32 acc. 2 CTAs/SM (81 KB smem each).
__global__ __launch_bounds__(256, 2)
void moe_mma_gemm(const float* __restrict__ bias, float* __restrict__ out) {
    extern __shared__ char smem[];
    const uint32_t sb = smem_u32(smem);
    int* rowid = reinterpret_cast<int*>(smem);
    const int tid = threadIdx.x;
    const int ntile = blockIdx.x;
    const int et = blockIdx.y;
    const int e = et >> 7;
    const int mtile = et & 127;
    const int cnt = g_cnt[e];
    const int m0 = mtile * BM;
    if (m0 >= cnt) return;

    if (tid < BM) rowid[tid] = (m0 + tid < cnt) ? g_list[e][m0 + tid] : -1;
    __syncthreads();

    const __nv_bfloat16* Whb = g_wh + ((size_t)e * D_MODEL + (size_t)ntile * BN) * D_MODEL;
    const __nv_bfloat16* Wlb = g_wl + ((size_t)e * D_MODEL + (size_t)ntile * BN) * D_MODEL;

    // ---- staging: per stage, per matrix 512 16B-chunks (128 rows x 4) ----
    auto stage_load = [&](int st, int c) {
        const int k0 = c * KC;
        const uint32_t base = sb + TILES_OFF + st * STAGE_BYTES;
        #pragma unroll
        for (int i = 0; i < 2; i++) {
            const int u = tid + i * 256;          // 0..511
            const int row = u >> 2, cc = u & 3;
            const uint32_t d = base + row * STRIDE_B + cc * 16;
            const int sv = rowid[row];
            const int sz = (sv >= 0) ? 16 : 0;
            const size_t aoff = (size_t)((sv >= 0) ? (sv >> 1) : 0) * D_MODEL + k0 + cc * 8;
            cp16(d + AH_OFF, g_hh + aoff, sz);
            cp16(d + AL_OFF, g_hl + aoff, sz);
            const size_t boff = (size_t)row * D_MODEL + k0 + cc * 8;
            cp16(d + BH_OFF, Whb + boff, 16);
            cp16(d + BL_OFF, Wlb + boff, 16);
        }
        cp_commit();
    };

    const int lane = tid & 31, wid = tid >> 5;
    const int wm = wid & 3;                     // 4 warps over 128 rows
    const int wn = wid >> 2;                    // 2 warps over 128 cols
    const uint32_t arow = (uint32_t)((wm * 32 + (lane & 15)) * STRIDE_B + (lane >> 4) * 16);
    const uint32_t brow = (uint32_t)((wn * 64 + (lane & 15)) * STRIDE_B + (lane >> 4) * 16);

    float acc[2][8][4];
    #pragma unroll
    for (int mf = 0; mf < 2; mf++)
        #pragma unroll
        for (int n8 = 0; n8 < 8; n8++)
            #pragma unroll
            for (int q = 0; q < 4; q++) acc[mf][n8][q] = 0.f;

    stage_load(0, 0);

    for (int c = 0; c < NCHUNK; c++) {
        if (c + 1 < NCHUNK) {
            stage_load((c + 1) & 1, c + 1);
            asm volatile("cp.async.wait_group 1;" ::: "memory");
        } else {
            asm volatile("cp.async.wait_group 0;" ::: "memory");
        }
        __syncthreads();

        const uint32_t stb = sb + TILES_OFF + (c & 1) * STAGE_BYTES;
        #pragma unroll
        for (int ks = 0; ks < 2; ks++) {
            const uint32_t koff = ks * 32;      // 16 bf16 = 32 B
            uint32_t ah[2][4], al[2][4];
            #pragma unroll
            for (int mf = 0; mf < 2; mf++) {
                ldsm4(ah[mf], stb + AH_OFF + arow + mf * (16 * STRIDE_B) + koff);
                ldsm4(al[mf], stb + AL_OFF + arow + mf * (16 * STRIDE_B) + koff);
            }
            uint32_t bh[8][2], bl[8][2];
            #pragma unroll
            for (int nf = 0; nf < 4; nf++) {
                uint32_t r[4];
                ldsm4(r, stb + BH_OFF + brow + nf * (16 * STRIDE_B) + koff);
                bh[nf * 2 + 0][0] = r[0]; bh[nf * 2 + 0][1] = r[2];
                bh[nf * 2 + 1][0] = r[1]; bh[nf * 2 + 1][1] = r[3];
                ldsm4(r, stb + BL_OFF + brow + nf * (16 * STRIDE_B) + koff);
                bl[nf * 2 + 0][0] = r[0]; bl[nf * 2 + 0][1] = r[2];
                bl[nf * 2 + 1][0] = r[1]; bl[nf * 2 + 1][1] = r[3];
            }
            #pragma unroll
            for (int mf = 0; mf < 2; mf++)
                #pragma unroll
                for (int n8 = 0; n8 < 8; n8++) {
                    mma16816(acc[mf][n8], ah[mf], bh[n8]);
                    mma16816(acc[mf][n8], al[mf], bh[n8]);
                    mma16816(acc[mf][n8], ah[mf], bl[n8]);
                }
        }
        __syncthreads();
    }

    // ---- epilogue: + bias, scatter rows to out (slot 0) / scr1 (slot 1) ----
    const int quad = lane >> 2, tq = lane & 3;
    #pragma unroll
    for (int mf = 0; mf < 2; mf++) {
        #pragma unroll
        for (int half = 0; half < 2; half++) {
            const int mrow = wm * 32 + mf * 16 + half * 8 + quad;
            const int sv = rowid[mrow];
            if (sv < 0) continue;
            float* dst = ((sv & 1) ? g_scr1 : out) + (size_t)(sv >> 1) * D_MODEL;
            #pragma unroll
            for (int n8 = 0; n8 < 8; n8++) {
                const int gcol = ntile * BN + wn * 64 + n8 * 8 + tq * 2;
                const float* bp = bias + e * D_MODEL + gcol;
                float2 o;
                o.x = acc[mf][n8][half * 2 + 0] + bp[0];
                o.y = acc[mf][n8][half * 2 + 1] + bp[1];
                *reinterpret_cast<float2*>(dst + gcol) = o;
            }
        }
    }
}

// ---------------- kernel: combine (out[t] += scr1[t]) -------------------------
__global__ void combine_kernel(float* __restrict__ out) {
    const long long n4 = (long long)T_TOKENS * D_MODEL / 4;
    const float4* s4 = reinterpret_cast<const float4*>(g_scr1);
    float4* o4 = reinterpret_cast<float4*>(out);
    for (long long i = (long long)blockIdx.x * blockDim.x + threadIdx.x; i < n4;
         i += (long long)gridDim.x * blockDim.x) {
        float4 a = o4[i];
        float4 b = s4[i];
        o4[i] = make_float4(a.x + b.x, a.y + b.y, a.z + b.z, a.w + b.w);
    }
}

// ---------------- launch ------------------------------------------------------
extern "C" void kernel_launch(void* const* d_in, const int* in_sizes, int n_in,
                              void* d_out, int out_size) {
    const float* h  = (const float*)d_in[0];   // [16384, 2048]
    const float* Wg = (const float*)d_in[1];   // [8, 2048]
    const float* bg = (const float*)d_in[2];   // [8]
    const float* W  = (const float*)d_in[3];   // [8, 2048, 2048]
    const float* b  = (const float*)d_in[4];   // [8, 2048]
    float* out = (float*)d_out;                // [16384, 2048]
    (void)in_sizes; (void)n_in; (void)out_size;

    init_kernel<<<1, 32>>>();

    __nv_bfloat16 *wh, *wl;
    cudaGetSymbolAddress((void**)&wh, g_wh);
    cudaGetSymbolAddress((void**)&wl, g_wl);

    prep_kernel<<<T_TOKENS / 4, 256>>>(h, Wg, bg);                 // h hi/lo + router
    convert_kernel<<<8192, 256>>>(W, wh, wl, (long long)N_EXP * D_MODEL * D_MODEL / 4);

    cudaFuncSetAttribute(moe_mma_gemm, cudaFuncAttributeMaxDynamicSharedMemorySize, SMEM_TOTAL);
    dim3 grid(NT, N_EXP * (T_TOKENS / BM));
    moe_mma_gemm<<<grid, 256, SMEM_TOTAL>>>(b, out);

    combine_kernel<<<2048, 256>>>(out);
}

// round 12
// speedup vs baseline: 3.5031x; 1.3536x over previous
#include <cuda_runtime.h>
#include <cuda_fp16.h>
#include <cstdint>
#include <cstddef>

#define T_TOKENS 16384
#define D_MODEL  2048
#define N_EXP    8

// GEMM tiling
#define BM 128
#define BN 128
#define KC 32                        // fp16 elems per staged K-chunk
#define NCHUNK (D_MODEL / KC)        // 64
#define NT (D_MODEL / BN)            // 16 n-tiles

// Staged row: 32 fp16 = 64 B data + 16 B pad = 80 B -> conflict-free ldmatrix
#define STRIDE_B 80
#define AH_OFF 0
#define AL_OFF 10240
#define B_OFF  20480
#define STAGE_BYTES 30720
#define NSTAGE 3
#define TILES_OFF 1024
#define SMEM_TOTAL (TILES_OFF + NSTAGE * STAGE_BYTES)   // 93184 -> 2 CTAs/SM

// ---------------- device scratch ---------------------------------------------
__device__ int g_cnt[N_EXP];
__device__ int g_list[N_EXP][T_TOKENS];                       // packed token*2+slot
__device__ __half g_hh[(size_t)T_TOKENS * D_MODEL];           // hidden fp16 hi
__device__ __half g_hl[(size_t)T_TOKENS * D_MODEL];           // hidden fp16 lo
__device__ __half g_w [(size_t)N_EXP * D_MODEL * D_MODEL];    // W fp16 (single)
__device__ float g_scr1[(size_t)T_TOKENS * D_MODEL];          // slot-1 outputs

// ---------------- helpers -----------------------------------------------------
__device__ __forceinline__ uint32_t smem_u32(const void* p) {
    uint32_t a;
    asm("{ .reg .u64 t; cvta.to.shared.u64 t, %1; cvt.u32.u64 %0, t; }" : "=r"(a) : "l"(p));
    return a;
}
__device__ __forceinline__ void cp16(uint32_t dst, const void* src, int sz) {
    asm volatile("cp.async.cg.shared.global [%0], [%1], 16, %2;"
                 :: "r"(dst), "l"(src), "r"(sz) : "memory");
}
__device__ __forceinline__ void cp_commit() {
    asm volatile("cp.async.commit_group;" ::: "memory");
}
__device__ __forceinline__ void ldsm4(uint32_t* r, uint32_t addr) {
    asm volatile("ldmatrix.sync.aligned.m8n8.x4.shared.b16 {%0,%1,%2,%3}, [%4];"
                 : "=r"(r[0]), "=r"(r[1]), "=r"(r[2]), "=r"(r[3]) : "r"(addr));
}
__device__ __forceinline__ void mma16816(float* d, const uint32_t* a, const uint32_t* b) {
    asm volatile(
        "mma.sync.aligned.m16n8k16.row.col.f32.f16.f16.f32 "
        "{%0,%1,%2,%3}, {%4,%5,%6,%7}, {%8,%9}, {%0,%1,%2,%3};"
        : "+f"(d[0]), "+f"(d[1]), "+f"(d[2]), "+f"(d[3])
        : "r"(a[0]), "r"(a[1]), "r"(a[2]), "r"(a[3]), "r"(b[0]), "r"(b[1]));
}

// ---------------- kernel: zero routing counters -------------------------------
__global__ void init_kernel() {
    if (threadIdx.x < N_EXP) g_cnt[threadIdx.x] = 0;
}

// ---------------- kernel: fused h convert (fp32 -> fp16 hi/lo) + router -------
__global__ __launch_bounds__(256) void prep_kernel(const float* __restrict__ h,
                                                   const float* __restrict__ Wg,
                                                   const float* __restrict__ bg) {
    __shared__ float sh[4 * D_MODEL];      // 32 KB
    __shared__ float slog[4][N_EXP];
    const int tid = threadIdx.x;
    const int t0 = blockIdx.x * 4;
    const size_t base = (size_t)t0 * D_MODEL;

    for (int i = tid * 4; i < 4 * D_MODEL; i += 256 * 4)
        *reinterpret_cast<float4*>(sh + i) =
            *reinterpret_cast<const float4*>(h + base + i);
    __syncthreads();

    for (int i = tid * 4; i < 4 * D_MODEL; i += 256 * 4) {
        float4 v = *reinterpret_cast<const float4*>(sh + i);
        __half h0 = __float2half_rn(v.x);
        __half h1 = __float2half_rn(v.y);
        __half h2 = __float2half_rn(v.z);
        __half h3 = __float2half_rn(v.w);
        __half l0 = __float2half_rn(v.x - __half2float(h0));
        __half l1 = __float2half_rn(v.y - __half2float(h1));
        __half l2 = __float2half_rn(v.z - __half2float(h2));
        __half l3 = __float2half_rn(v.w - __half2float(h3));
        *reinterpret_cast<__half2*>(g_hh + base + i)     = __half2(h0, h1);
        *reinterpret_cast<__half2*>(g_hh + base + i + 2) = __half2(h2, h3);
        *reinterpret_cast<__half2*>(g_hl + base + i)     = __half2(l0, l1);
        *reinterpret_cast<__half2*>(g_hl + base + i + 2) = __half2(l2, l3);
    }

    const int w = tid >> 5, lane = tid & 31;
    float wreg[64];
    #pragma unroll
    for (int j = 0; j < 64; j++) wreg[j] = Wg[w * D_MODEL + lane + j * 32];

    #pragma unroll
    for (int tk = 0; tk < 4; tk++) {
        float s = 0.f;
        #pragma unroll
        for (int j = 0; j < 64; j++) s += sh[tk * D_MODEL + lane + j * 32] * wreg[j];
        #pragma unroll
        for (int o = 16; o > 0; o >>= 1) s += __shfl_xor_sync(0xffffffffu, s, o);
        if (lane == 0) slog[tk][w] = s + bg[w];
    }
    __syncthreads();

    if (tid < 4) {
        const int token = t0 + tid;
        int b0 = 0; float v0 = slog[tid][0];
        #pragma unroll
        for (int i = 1; i < N_EXP; i++) if (slog[tid][i] > v0) { v0 = slog[tid][i]; b0 = i; }
        int b1 = -1; float v1 = -3.402823466e38f;
        #pragma unroll
        for (int i = 0; i < N_EXP; i++)
            if (i != b0 && slog[tid][i] > v1) { v1 = slog[tid][i]; b1 = i; }
        int p0 = atomicAdd(&g_cnt[b0], 1); g_list[b0][p0] = token * 2;       // -> out
        int p1 = atomicAdd(&g_cnt[b1], 1); g_list[b1][p1] = token * 2 + 1;   // -> scr1
    }
}

// ---------------- kernel: W fp32 -> fp16 --------------------------------------
__global__ void convert_w_kernel(const float* __restrict__ src, long long n4) {
    long long i = (long long)blockIdx.x * blockDim.x + threadIdx.x;
    for (; i < n4; i += (long long)gridDim.x * blockDim.x) {
        float4 v = reinterpret_cast<const float4*>(src)[i];
        __half2 p0 = __half2(__float2half_rn(v.x), __float2half_rn(v.y));
        __half2 p1 = __half2(__float2half_rn(v.z), __float2half_rn(v.w));
        reinterpret_cast<__half2*>(g_w)[i * 2 + 0] = p0;
        reinterpret_cast<__half2*>(g_w)[i * 2 + 1] = p1;
    }
}

// ---------------- kernel: grouped GEMM, fp16 A-split (2 MMAs / fragment) ------
// grid.x = ntile (16), grid.y = e*128 + mtile. 256 threads = 8 warps (4m x 2n).
// Warp tile 32x64, m16n8k16 f16 x f16 -> f32. 3-stage cp.async, 2 CTAs/SM.
__global__ __launch_bounds__(256, 2)
void moe_mma_gemm(const float* __restrict__ bias, float* __restrict__ out) {
    extern __shared__ char smem[];
    const uint32_t sb = smem_u32(smem);
    int* rowid = reinterpret_cast<int*>(smem);
    const int tid = threadIdx.x;
    const int ntile = blockIdx.x;
    const int et = blockIdx.y;
    const int e = et >> 7;
    const int mtile = et & 127;
    const int cnt = g_cnt[e];
    const int m0 = mtile * BM;
    if (m0 >= cnt) return;

    if (tid < BM) rowid[tid] = (m0 + tid < cnt) ? g_list[e][m0 + tid] : -1;
    __syncthreads();

    const __half* Wb = g_w + ((size_t)e * D_MODEL + (size_t)ntile * BN) * D_MODEL;

    // ---- staging: per stage 512 row-chunks (128 rows x 4 chunks of 16B) ----
    auto stage_load = [&](int st, int c) {
        const int k0 = c * KC;
        const uint32_t base = sb + TILES_OFF + st * STAGE_BYTES;
        #pragma unroll
        for (int i = 0; i < 2; i++) {
            const int u = tid + i * 256;          // 0..511
            const int row = u >> 2, cc = u & 3;
            const uint32_t d = base + row * STRIDE_B + cc * 16;
            const int sv = rowid[row];
            const int sz = (sv >= 0) ? 16 : 0;
            const size_t aoff = (size_t)((sv >= 0) ? (sv >> 1) : 0) * D_MODEL + k0 + cc * 8;
            cp16(d + AH_OFF, g_hh + aoff, sz);
            cp16(d + AL_OFF, g_hl + aoff, sz);
            const size_t boff = (size_t)row * D_MODEL + k0 + cc * 8;
            cp16(d + B_OFF, Wb + boff, 16);
        }
        cp_commit();
    };

    const int lane = tid & 31, wid = tid >> 5;
    const int wm = wid & 3;                     // 4 warps over 128 rows
    const int wn = wid >> 2;                    // 2 warps over 128 cols
    const uint32_t arow = (uint32_t)((wm * 32 + (lane & 15)) * STRIDE_B + (lane >> 4) * 16);
    const uint32_t brow = (uint32_t)((wn * 64 + (lane & 15)) * STRIDE_B + (lane >> 4) * 16);

    float acc[2][8][4];
    #pragma unroll
    for (int mf = 0; mf < 2; mf++)
        #pragma unroll
        for (int n8 = 0; n8 < 8; n8++)
            #pragma unroll
            for (int q = 0; q < 4; q++) acc[mf][n8][q] = 0.f;

    stage_load(0, 0);
    stage_load(1, 1);

    int st = 0;
    for (int c = 0; c < NCHUNK; c++) {
        if (c + 2 < NCHUNK) {
            stage_load((st + 2) % NSTAGE, c + 2);
            asm volatile("cp.async.wait_group 2;" ::: "memory");
        } else if (c + 1 < NCHUNK) {
            asm volatile("cp.async.wait_group 1;" ::: "memory");
        } else {
            asm volatile("cp.async.wait_group 0;" ::: "memory");
        }
        __syncthreads();

        const uint32_t stb = sb + TILES_OFF + st * STAGE_BYTES;
        #pragma unroll
        for (int ks = 0; ks < 2; ks++) {
            const uint32_t koff = ks * 32;      // 16 fp16 = 32 B
            uint32_t ah[2][4], al[2][4];
            #pragma unroll
            for (int mf = 0; mf < 2; mf++) {
                ldsm4(ah[mf], stb + AH_OFF + arow + mf * (16 * STRIDE_B) + koff);
                ldsm4(al[mf], stb + AL_OFF + arow + mf * (16 * STRIDE_B) + koff);
            }
            uint32_t bb[8][2];
            #pragma unroll
            for (int nf = 0; nf < 4; nf++) {
                uint32_t r[4];
                ldsm4(r, stb + B_OFF + brow + nf * (16 * STRIDE_B) + koff);
                bb[nf * 2 + 0][0] = r[0]; bb[nf * 2 + 0][1] = r[2];
                bb[nf * 2 + 1][0] = r[1]; bb[nf * 2 + 1][1] = r[3];
            }
            #pragma unroll
            for (int mf = 0; mf < 2; mf++)
                #pragma unroll
                for (int n8 = 0; n8 < 8; n8++) {
                    mma16816(acc[mf][n8], ah[mf], bb[n8]);
                    mma16816(acc[mf][n8], al[mf], bb[n8]);
                }
        }
        __syncthreads();
        st = (st + 1) % NSTAGE;
    }

    // ---- epilogue: + bias, scatter rows to out (slot 0) / scr1 (slot 1) ----
    const int quad = lane >> 2, tq = lane & 3;
    #pragma unroll
    for (int mf = 0; mf < 2; mf++) {
        #pragma unroll
        for (int half = 0; half < 2; half++) {
            const int mrow = wm * 32 + mf * 16 + half * 8 + quad;
            const int sv = rowid[mrow];
            if (sv < 0) continue;
            float* dst = ((sv & 1) ? g_scr1 : out) + (size_t)(sv >> 1) * D_MODEL;
            #pragma unroll
            for (int n8 = 0; n8 < 8; n8++) {
                const int gcol = ntile * BN + wn * 64 + n8 * 8 + tq * 2;
                const float* bp = bias + e * D_MODEL + gcol;
                float2 o;
                o.x = acc[mf][n8][half * 2 + 0] + bp[0];
                o.y = acc[mf][n8][half * 2 + 1] + bp[1];
                *reinterpret_cast<float2*>(dst + gcol) = o;
            }
        }
    }
}

// ---------------- kernel: combine (out[t] += scr1[t]) -------------------------
__global__ void combine_kernel(float* __restrict__ out) {
    const long long n4 = (long long)T_TOKENS * D_MODEL / 4;
    const float4* s4 = reinterpret_cast<const float4*>(g_scr1);
    float4* o4 = reinterpret_cast<float4*>(out);
    for (long long i = (long long)blockIdx.x * blockDim.x + threadIdx.x; i < n4;
         i += (long long)gridDim.x * blockDim.x) {
        float4 a = o4[i];
        float4 b = s4[i];
        o4[i] = make_float4(a.x + b.x, a.y + b.y, a.z + b.z, a.w + b.w);
    }
}

// ---------------- launch ------------------------------------------------------
extern "C" void kernel_launch(void* const* d_in, const int* in_sizes, int n_in,
                              void* d_out, int out_size) {
    const float* h  = (const float*)d_in[0];   // [16384, 2048]
    const float* Wg = (const float*)d_in[1];   // [8, 2048]
    const float* bg = (const float*)d_in[2];   // [8]
    const float* W  = (const float*)d_in[3];   // [8, 2048, 2048]
    const float* b  = (const float*)d_in[4];   // [8, 2048]
    float* out = (float*)d_out;                // [16384, 2048]
    (void)in_sizes; (void)n_in; (void)out_size;

    init_kernel<<<1, 32>>>();

    prep_kernel<<<T_TOKENS / 4, 256>>>(h, Wg, bg);                 // h hi/lo + router
    convert_w_kernel<<<8192, 256>>>(W, (long long)N_EXP * D_MODEL * D_MODEL / 4);

    cudaFuncSetAttribute(moe_mma_gemm, cudaFuncAttributeMaxDynamicSharedMemorySize, SMEM_TOTAL);
    dim3 grid(NT, N_EXP * (T_TOKENS / BM));
    moe_mma_gemm<<<grid, 256, SMEM_TOTAL>>>(b, out);

    combine_kernel<<<2048, 256>>>(out);
}

// round 13
// speedup vs baseline: 6.0547x; 1.7284x over previous
#include <cuda_runtime.h>
#include <cuda_fp16.h>
#include <cstdint>
#include <cstddef>

#define T_TOKENS 16384
#define D_MODEL  2048
#define N_EXP    8

// GEMM tiling
#define BM 128
#define BN 128
#define KC 32                        // fp16 elems per staged K-chunk
#define NCHUNK (D_MODEL / KC)        // 64
#define NT (D_MODEL / BN)            // 16 n-tiles

// Staged row: 32 fp16 = 64 B data + 16 B pad = 80 B -> conflict-free ldmatrix
#define STRIDE_B 80
#define A_OFF 0
#define B_OFF 10240
#define STAGE_BYTES 20480
#define NSTAGE 4
#define TILES_OFF 1024
#define SMEM_TOTAL (TILES_OFF + NSTAGE * STAGE_BYTES)   // 82944 -> 2 CTAs/SM

// ---------------- device scratch ---------------------------------------------
__device__ int g_cnt[N_EXP];
__device__ int g_list[N_EXP][T_TOKENS];                       // packed token*2+slot
__device__ __half g_h [(size_t)T_TOKENS * D_MODEL];           // hidden fp16
__device__ __half g_w [(size_t)N_EXP * D_MODEL * D_MODEL];    // W fp16
__device__ float g_scr1[(size_t)T_TOKENS * D_MODEL];          // slot-1 outputs

// ---------------- helpers -----------------------------------------------------
__device__ __forceinline__ uint32_t smem_u32(const void* p) {
    uint32_t a;
    asm("{ .reg .u64 t; cvta.to.shared.u64 t, %1; cvt.u32.u64 %0, t; }" : "=r"(a) : "l"(p));
    return a;
}
__device__ __forceinline__ void cp16(uint32_t dst, const void* src, int sz) {
    asm volatile("cp.async.cg.shared.global [%0], [%1], 16, %2;"
                 :: "r"(dst), "l"(src), "r"(sz) : "memory");
}
__device__ __forceinline__ void cp_commit() {
    asm volatile("cp.async.commit_group;" ::: "memory");
}
__device__ __forceinline__ void ldsm4(uint32_t* r, uint32_t addr) {
    asm volatile("ldmatrix.sync.aligned.m8n8.x4.shared.b16 {%0,%1,%2,%3}, [%4];"
                 : "=r"(r[0]), "=r"(r[1]), "=r"(r[2]), "=r"(r[3]) : "r"(addr));
}
__device__ __forceinline__ void mma16816(float* d, const uint32_t* a, const uint32_t* b) {
    asm volatile(
        "mma.sync.aligned.m16n8k16.row.col.f32.f16.f16.f32 "
        "{%0,%1,%2,%3}, {%4,%5,%6,%7}, {%8,%9}, {%0,%1,%2,%3};"
        : "+f"(d[0]), "+f"(d[1]), "+f"(d[2]), "+f"(d[3])
        : "r"(a[0]), "r"(a[1]), "r"(a[2]), "r"(a[3]), "r"(b[0]), "r"(b[1]));
}

// ---------------- kernel: zero routing counters -------------------------------
__global__ void init_kernel() {
    if (threadIdx.x < N_EXP) g_cnt[threadIdx.x] = 0;
}

// ---------------- kernel: fused h convert (fp32 -> fp16) + router -------------
__global__ __launch_bounds__(256) void prep_kernel(const float* __restrict__ h,
                                                   const float* __restrict__ Wg,
                                                   const float* __restrict__ bg) {
    __shared__ float sh[4 * D_MODEL];      // 32 KB
    __shared__ float slog[4][N_EXP];
    const int tid = threadIdx.x;
    const int t0 = blockIdx.x * 4;
    const size_t base = (size_t)t0 * D_MODEL;

    for (int i = tid * 4; i < 4 * D_MODEL; i += 256 * 4)
        *reinterpret_cast<float4*>(sh + i) =
            *reinterpret_cast<const float4*>(h + base + i);
    __syncthreads();

    for (int i = tid * 4; i < 4 * D_MODEL; i += 256 * 4) {
        float4 v = *reinterpret_cast<const float4*>(sh + i);
        __half2 p0 = __half2(__float2half_rn(v.x), __float2half_rn(v.y));
        __half2 p1 = __half2(__float2half_rn(v.z), __float2half_rn(v.w));
        *reinterpret_cast<__half2*>(g_h + base + i)     = p0;
        *reinterpret_cast<__half2*>(g_h + base + i + 2) = p1;
    }

    const int w = tid >> 5, lane = tid & 31;
    float wreg[64];
    #pragma unroll
    for (int j = 0; j < 64; j++) wreg[j] = Wg[w * D_MODEL + lane + j * 32];

    #pragma unroll
    for (int tk = 0; tk < 4; tk++) {
        float s = 0.f;
        #pragma unroll
        for (int j = 0; j < 64; j++) s += sh[tk * D_MODEL + lane + j * 32] * wreg[j];
        #pragma unroll
        for (int o = 16; o > 0; o >>= 1) s += __shfl_xor_sync(0xffffffffu, s, o);
        if (lane == 0) slog[tk][w] = s + bg[w];
    }
    __syncthreads();

    if (tid < 4) {
        const int token = t0 + tid;
        int b0 = 0; float v0 = slog[tid][0];
        #pragma unroll
        for (int i = 1; i < N_EXP; i++) if (slog[tid][i] > v0) { v0 = slog[tid][i]; b0 = i; }
        int b1 = -1; float v1 = -3.402823466e38f;
        #pragma unroll
        for (int i = 0; i < N_EXP; i++)
            if (i != b0 && slog[tid][i] > v1) { v1 = slog[tid][i]; b1 = i; }
        int p0 = atomicAdd(&g_cnt[b0], 1); g_list[b0][p0] = token * 2;       // -> out
        int p1 = atomicAdd(&g_cnt[b1], 1); g_list[b1][p1] = token * 2 + 1;   // -> scr1
    }
}

// ---------------- kernel: W fp32 -> fp16 --------------------------------------
__global__ void convert_w_kernel(const float* __restrict__ src, long long n4) {
    long long i = (long long)blockIdx.x * blockDim.x + threadIdx.x;
    for (; i < n4; i += (long long)gridDim.x * blockDim.x) {
        float4 v = reinterpret_cast<const float4*>(src)[i];
        __half2 p0 = __half2(__float2half_rn(v.x), __float2half_rn(v.y));
        __half2 p1 = __half2(__float2half_rn(v.z), __float2half_rn(v.w));
        reinterpret_cast<__half2*>(g_w)[i * 2 + 0] = p0;
        reinterpret_cast<__half2*>(g_w)[i * 2 + 1] = p1;
    }
}

// ---------------- kernel: grouped GEMM, plain fp16 x fp16 -> fp32 -------------
// grid.x = ntile (16), grid.y = e*128 + mtile. 256 threads = 8 warps (4m x 2n).
// Warp tile 32x64, m16n8k16. 4-stage cp.async pipeline, 2 CTAs/SM.
__global__ __launch_bounds__(256, 2)
void moe_mma_gemm(const float* __restrict__ bias, float* __restrict__ out) {
    extern __shared__ char smem[];
    const uint32_t sb = smem_u32(smem);
    int* rowid = reinterpret_cast<int*>(smem);
    const int tid = threadIdx.x;
    const int ntile = blockIdx.x;
    const int et = blockIdx.y;
    const int e = et >> 7;
    const int mtile = et & 127;
    const int cnt = g_cnt[e];
    const int m0 = mtile * BM;
    if (m0 >= cnt) return;

    if (tid < BM) rowid[tid] = (m0 + tid < cnt) ? g_list[e][m0 + tid] : -1;
    __syncthreads();

    const __half* Wb = g_w + ((size_t)e * D_MODEL + (size_t)ntile * BN) * D_MODEL;

    // ---- staging: per stage, A + B each 512 16B-chunks (128 rows x 4) ----
    auto stage_load = [&](int st, int c) {
        const int k0 = c * KC;
        const uint32_t base = sb + TILES_OFF + st * STAGE_BYTES;
        #pragma unroll
        for (int i = 0; i < 2; i++) {
            const int u = tid + i * 256;          // 0..511
            const int row = u >> 2, cc = u & 3;
            const uint32_t d = base + row * STRIDE_B + cc * 16;
            const int sv = rowid[row];
            const int sz = (sv >= 0) ? 16 : 0;
            const size_t aoff = (size_t)((sv >= 0) ? (sv >> 1) : 0) * D_MODEL + k0 + cc * 8;
            cp16(d + A_OFF, g_h + aoff, sz);
            const size_t boff = (size_t)row * D_MODEL + k0 + cc * 8;
            cp16(d + B_OFF, Wb + boff, 16);
        }
        cp_commit();
    };

    const int lane = tid & 31, wid = tid >> 5;
    const int wm = wid & 3;                     // 4 warps over 128 rows
    const int wn = wid >> 2;                    // 2 warps over 128 cols
    const uint32_t arow = (uint32_t)((wm * 32 + (lane & 15)) * STRIDE_B + (lane >> 4) * 16);
    const uint32_t brow = (uint32_t)((wn * 64 + (lane & 15)) * STRIDE_B + (lane >> 4) * 16);

    float acc[2][8][4];
    #pragma unroll
    for (int mf = 0; mf < 2; mf++)
        #pragma unroll
        for (int n8 = 0; n8 < 8; n8++)
            #pragma unroll
            for (int q = 0; q < 4; q++) acc[mf][n8][q] = 0.f;

    stage_load(0, 0);
    stage_load(1, 1);
    stage_load(2, 2);

    int st = 0;
    for (int c = 0; c < NCHUNK; c++) {
        if (c + 3 < NCHUNK) {
            asm volatile("cp.async.wait_group 2;" ::: "memory");
        } else if (c + 2 < NCHUNK) {
            asm volatile("cp.async.wait_group 2;" ::: "memory");
        } else if (c + 1 < NCHUNK) {
            asm volatile("cp.async.wait_group 1;" ::: "memory");
        } else {
            asm volatile("cp.async.wait_group 0;" ::: "memory");
        }
        __syncthreads();

        const uint32_t stb = sb + TILES_OFF + st * STAGE_BYTES;
        #pragma unroll
        for (int ks = 0; ks < 2; ks++) {
            const uint32_t koff = ks * 32;      // 16 fp16 = 32 B
            uint32_t aa[2][4];
            #pragma unroll
            for (int mf = 0; mf < 2; mf++)
                ldsm4(aa[mf], stb + A_OFF + arow + mf * (16 * STRIDE_B) + koff);
            uint32_t bb[8][2];
            #pragma unroll
            for (int nf = 0; nf < 4; nf++) {
                uint32_t r[4];
                ldsm4(r, stb + B_OFF + brow + nf * (16 * STRIDE_B) + koff);
                bb[nf * 2 + 0][0] = r[0]; bb[nf * 2 + 0][1] = r[2];
                bb[nf * 2 + 1][0] = r[1]; bb[nf * 2 + 1][1] = r[3];
            }
            #pragma unroll
            for (int mf = 0; mf < 2; mf++)
                #pragma unroll
                for (int n8 = 0; n8 < 8; n8++)
                    mma16816(acc[mf][n8], aa[mf], bb[n8]);
        }
        __syncthreads();

        if (c + 3 < NCHUNK) stage_load((st + 3) % NSTAGE, c + 3);
        st = (st + 1) % NSTAGE;
    }

    // ---- epilogue: + bias, scatter rows to out (slot 0) / scr1 (slot 1) ----
    const int quad = lane >> 2, tq = lane & 3;
    #pragma unroll
    for (int mf = 0; mf < 2; mf++) {
        #pragma unroll
        for (int half = 0; half < 2; half++) {
            const int mrow = wm * 32 + mf * 16 + half * 8 + quad;
            const int sv = rowid[mrow];
            if (sv < 0) continue;
            float* dst = ((sv & 1) ? g_scr1 : out) + (size_t)(sv >> 1) * D_MODEL;
            #pragma unroll
            for (int n8 = 0; n8 < 8; n8++) {
                const int gcol = ntile * BN + wn * 64 + n8 * 8 + tq * 2;
                const float* bp = bias + e * D_MODEL + gcol;
                float2 o;
                o.x = acc[mf][n8][half * 2 + 0] + bp[0];
                o.y = acc[mf][n8][half * 2 + 1] + bp[1];
                *reinterpret_cast<float2*>(dst + gcol) = o;
            }
        }
    }
}

// ---------------- kernel: combine (out[t] += scr1[t]) -------------------------
__global__ void combine_kernel(float* __restrict__ out) {
    const long long n4 = (long long)T_TOKENS * D_MODEL / 4;
    const float4* s4 = reinterpret_cast<const float4*>(g_scr1);
    float4* o4 = reinterpret_cast<float4*>(out);
    for (long long i = (long long)blockIdx.x * blockDim.x + threadIdx.x; i < n4;
         i += (long long)gridDim.x * blockDim.x) {
        float4 a = o4[i];
        float4 b = s4[i];
        o4[i] = make_float4(a.x + b.x, a.y + b.y, a.z + b.z, a.w + b.w);
    }
}

// ---------------- launch ------------------------------------------------------
extern "C" void kernel_launch(void* const* d_in, const int* in_sizes, int n_in,
                              void* d_out, int out_size) {
    const float* h  = (const float*)d_in[0];   // [16384, 2048]
    const float* Wg = (const float*)d_in[1];   // [8, 2048]
    const float* bg = (const float*)d_in[2];   // [8]
    const float* W  = (const float*)d_in[3];   // [8, 2048, 2048]
    const float* b  = (const float*)d_in[4];   // [8, 2048]
    float* out = (float*)d_out;                // [16384, 2048]
    (void)in_sizes; (void)n_in; (void)out_size;

    init_kernel<<<1, 32>>>();

    prep_kernel<<<T_TOKENS / 4, 256>>>(h, Wg, bg);                 // h fp16 + router
    convert_w_kernel<<<8192, 256>>>(W, (long long)N_EXP * D_MODEL * D_MODEL / 4);

    cudaFuncSetAttribute(moe_mma_gemm, cudaFuncAttributeMaxDynamicSharedMemorySize, SMEM_TOTAL);
    dim3 grid(NT, N_EXP * (T_TOKENS / BM));
    moe_mma_gemm<<<grid, 256, SMEM_TOTAL>>>(b, out);

    combine_kernel<<<2048, 256>>>(out);
}

// round 14
// speedup vs baseline: 6.3142x; 1.0429x over previous
#include <cuda_runtime.h>
#include <cuda_fp16.h>
#include <cstdint>
#include <cstddef>

#define T_TOKENS 16384
#define D_MODEL  2048
#define N_EXP    8

// GEMM tiling
#define BM 128
#define BN 128
#define KC 64                        // fp16 elems per staged K-chunk
#define NCHUNK (D_MODEL / KC)        // 32
#define NT (D_MODEL / BN)            // 16 n-tiles

// Staged row: 64 fp16 = 128 B data + 16 B pad = 144 B -> conflict-free ldmatrix
// (row offset words 36r mod 32 = 4r mod 32 -> 8 distinct quads)
#define STRIDE_B 144
#define A_OFF 0
#define B_OFF 18432
#define STAGE_BYTES 36864
#define NSTAGE 3
#define TILES_OFF 1024
#define SMEM_TOTAL (TILES_OFF + NSTAGE * STAGE_BYTES)   // 111616 -> 2 CTAs/SM

// ---------------- device scratch ---------------------------------------------
__device__ int g_cnt[N_EXP];
__device__ int g_list[N_EXP][T_TOKENS];                       // packed token*2+slot
__device__ __half g_h [(size_t)T_TOKENS * D_MODEL];           // hidden fp16
__device__ __half g_w [(size_t)N_EXP * D_MODEL * D_MODEL];    // W fp16
__device__ float g_scr1[(size_t)T_TOKENS * D_MODEL];          // slot-1 outputs

// ---------------- helpers -----------------------------------------------------
__device__ __forceinline__ uint32_t smem_u32(const void* p) {
    uint32_t a;
    asm("{ .reg .u64 t; cvta.to.shared.u64 t, %1; cvt.u32.u64 %0, t; }" : "=r"(a) : "l"(p));
    return a;
}
__device__ __forceinline__ void cp16(uint32_t dst, const void* src, int sz) {
    asm volatile("cp.async.cg.shared.global [%0], [%1], 16, %2;"
                 :: "r"(dst), "l"(src), "r"(sz) : "memory");
}
__device__ __forceinline__ void cp_commit() {
    asm volatile("cp.async.commit_group;" ::: "memory");
}
__device__ __forceinline__ void ldsm4(uint32_t* r, uint32_t addr) {
    asm volatile("ldmatrix.sync.aligned.m8n8.x4.shared.b16 {%0,%1,%2,%3}, [%4];"
                 : "=r"(r[0]), "=r"(r[1]), "=r"(r[2]), "=r"(r[3]) : "r"(addr));
}
__device__ __forceinline__ void mma16816(float* d, const uint32_t* a, const uint32_t* b) {
    asm volatile(
        "mma.sync.aligned.m16n8k16.row.col.f32.f16.f16.f32 "
        "{%0,%1,%2,%3}, {%4,%5,%6,%7}, {%8,%9}, {%0,%1,%2,%3};"
        : "+f"(d[0]), "+f"(d[1]), "+f"(d[2]), "+f"(d[3])
        : "r"(a[0]), "r"(a[1]), "r"(a[2]), "r"(a[3]), "r"(b[0]), "r"(b[1]));
}

// ---------------- kernel: zero routing counters -------------------------------
__global__ void init_kernel() {
    if (threadIdx.x < N_EXP) g_cnt[threadIdx.x] = 0;
}

// ---------------- kernel: fused h convert (fp32 -> fp16) + router -------------
__global__ __launch_bounds__(256) void prep_kernel(const float* __restrict__ h,
                                                   const float* __restrict__ Wg,
                                                   const float* __restrict__ bg) {
    __shared__ float sh[4 * D_MODEL];      // 32 KB
    __shared__ float slog[4][N_EXP];
    const int tid = threadIdx.x;
    const int t0 = blockIdx.x * 4;
    const size_t base = (size_t)t0 * D_MODEL;

    for (int i = tid * 4; i < 4 * D_MODEL; i += 256 * 4)
        *reinterpret_cast<float4*>(sh + i) =
            *reinterpret_cast<const float4*>(h + base + i);
    __syncthreads();

    for (int i = tid * 4; i < 4 * D_MODEL; i += 256 * 4) {
        float4 v = *reinterpret_cast<const float4*>(sh + i);
        __half2 p0 = __half2(__float2half_rn(v.x), __float2half_rn(v.y));
        __half2 p1 = __half2(__float2half_rn(v.z), __float2half_rn(v.w));
        *reinterpret_cast<__half2*>(g_h + base + i)     = p0;
        *reinterpret_cast<__half2*>(g_h + base + i + 2) = p1;
    }

    const int w = tid >> 5, lane = tid & 31;
    float wreg[64];
    #pragma unroll
    for (int j = 0; j < 64; j++) wreg[j] = Wg[w * D_MODEL + lane + j * 32];

    #pragma unroll
    for (int tk = 0; tk < 4; tk++) {
        float s = 0.f;
        #pragma unroll
        for (int j = 0; j < 64; j++) s += sh[tk * D_MODEL + lane + j * 32] * wreg[j];
        #pragma unroll
        for (int o = 16; o > 0; o >>= 1) s += __shfl_xor_sync(0xffffffffu, s, o);
        if (lane == 0) slog[tk][w] = s + bg[w];
    }
    __syncthreads();

    if (tid < 4) {
        const int token = t0 + tid;
        int b0 = 0; float v0 = slog[tid][0];
        #pragma unroll
        for (int i = 1; i < N_EXP; i++) if (slog[tid][i] > v0) { v0 = slog[tid][i]; b0 = i; }
        int b1 = -1; float v1 = -3.402823466e38f;
        #pragma unroll
        for (int i = 0; i < N_EXP; i++)
            if (i != b0 && slog[tid][i] > v1) { v1 = slog[tid][i]; b1 = i; }
        int p0 = atomicAdd(&g_cnt[b0], 1); g_list[b0][p0] = token * 2;       // -> out
        int p1 = atomicAdd(&g_cnt[b1], 1); g_list[b1][p1] = token * 2 + 1;   // -> scr1
    }
}

// ---------------- kernel: W fp32 -> fp16 --------------------------------------
__global__ void convert_w_kernel(const float* __restrict__ src, long long n4) {
    long long i = (long long)blockIdx.x * blockDim.x + threadIdx.x;
    for (; i < n4; i += (long long)gridDim.x * blockDim.x) {
        float4 v = reinterpret_cast<const float4*>(src)[i];
        __half2 p0 = __half2(__float2half_rn(v.x), __float2half_rn(v.y));
        __half2 p1 = __half2(__float2half_rn(v.z), __float2half_rn(v.w));
        reinterpret_cast<__half2*>(g_w)[i * 2 + 0] = p0;
        reinterpret_cast<__half2*>(g_w)[i * 2 + 1] = p1;
    }
}

// ---------------- kernel: grouped GEMM, fp16 x fp16 -> fp32 -------------------
// grid.x = ntile (16), grid.y = e*128 + mtile. 256 threads = 8 warps (4m x 2n).
// Warp tile 32x64, m16n8k16. KC=64, 3-stage cp.async, 2 CTAs/SM.
// Per-thread gather pointers hoisted out of the mainloop.
__global__ __launch_bounds__(256, 2)
void moe_mma_gemm(const float* __restrict__ bias, float* __restrict__ out) {
    extern __shared__ char smem[];
    const uint32_t sb = smem_u32(smem);
    int* rowid = reinterpret_cast<int*>(smem);
    const int tid = threadIdx.x;
    const int ntile = blockIdx.x;
    const int et = blockIdx.y;
    const int e = et >> 7;
    const int mtile = et & 127;
    const int cnt = g_cnt[e];
    const int m0 = mtile * BM;
    if (m0 >= cnt) return;

    if (tid < BM) rowid[tid] = (m0 + tid < cnt) ? g_list[e][m0 + tid] : -1;
    __syncthreads();

    const __half* Wb = g_w + ((size_t)e * D_MODEL + (size_t)ntile * BN) * D_MODEL;

    // ---- precompute per-thread staging pointers (loop-invariant) -----------
    // Per stage: A and B each 1024 16B-chunks (128 rows x 8); 4 per thread each.
    const char* asrc[4]; int asz[4];
    const char* bsrc[4];
    uint32_t doff[4];
    #pragma unroll
    for (int i = 0; i < 4; i++) {
        const int u = tid + i * 256;              // 0..1023
        const int row = u >> 3, cc = u & 7;
        doff[i] = (uint32_t)(row * STRIDE_B + cc * 16);
        const int sv = rowid[row];
        asz[i] = (sv >= 0) ? 16 : 0;
        asrc[i] = reinterpret_cast<const char*>(
            g_h + (size_t)((sv >= 0) ? (sv >> 1) : 0) * D_MODEL + cc * 8);
        bsrc[i] = reinterpret_cast<const char*>(Wb + (size_t)row * D_MODEL + cc * 8);
    }
    __syncthreads();

    auto stage_load = [&](int st, int c) {
        const uint32_t base = sb + TILES_OFF + st * STAGE_BYTES;
        const size_t kadv = (size_t)c * (KC * 2);     // bytes along K
        #pragma unroll
        for (int i = 0; i < 4; i++) {
            cp16(base + A_OFF + doff[i], asrc[i] + kadv, asz[i]);
            cp16(base + B_OFF + doff[i], bsrc[i] + kadv, 16);
        }
        cp_commit();
    };

    const int lane = tid & 31, wid = tid >> 5;
    const int wm = wid & 3;                     // 4 warps over 128 rows
    const int wn = wid >> 2;                    // 2 warps over 128 cols
    const uint32_t arow = (uint32_t)((wm * 32 + (lane & 15)) * STRIDE_B + (lane >> 4) * 16);
    const uint32_t brow = (uint32_t)((wn * 64 + (lane & 15)) * STRIDE_B + (lane >> 4) * 16);

    float acc[2][8][4];
    #pragma unroll
    for (int mf = 0; mf < 2; mf++)
        #pragma unroll
        for (int n8 = 0; n8 < 8; n8++)
            #pragma unroll
            for (int q = 0; q < 4; q++) acc[mf][n8][q] = 0.f;

    stage_load(0, 0);
    stage_load(1, 1);

    int st = 0;
    for (int c = 0; c < NCHUNK; c++) {
        if (c + 2 < NCHUNK) {
            stage_load((st + 2) % NSTAGE, c + 2);
            asm volatile("cp.async.wait_group 2;" ::: "memory");
        } else if (c + 1 < NCHUNK) {
            asm volatile("cp.async.wait_group 1;" ::: "memory");
        } else {
            asm volatile("cp.async.wait_group 0;" ::: "memory");
        }
        __syncthreads();

        const uint32_t stb = sb + TILES_OFF + st * STAGE_BYTES;
        #pragma unroll
        for (int ks = 0; ks < 4; ks++) {
            const uint32_t koff = ks * 32;      // 16 fp16 = 32 B
            uint32_t aa[2][4];
            #pragma unroll
            for (int mf = 0; mf < 2; mf++)
                ldsm4(aa[mf], stb + A_OFF + arow + mf * (16 * STRIDE_B) + koff);
            uint32_t bb[8][2];
            #pragma unroll
            for (int nf = 0; nf < 4; nf++) {
                uint32_t r[4];
                ldsm4(r, stb + B_OFF + brow + nf * (16 * STRIDE_B) + koff);
                bb[nf * 2 + 0][0] = r[0]; bb[nf * 2 + 0][1] = r[2];
                bb[nf * 2 + 1][0] = r[1]; bb[nf * 2 + 1][1] = r[3];
            }
            #pragma unroll
            for (int mf = 0; mf < 2; mf++)
                #pragma unroll
                for (int n8 = 0; n8 < 8; n8++)
                    mma16816(acc[mf][n8], aa[mf], bb[n8]);
        }
        __syncthreads();
        st = (st + 1) % NSTAGE;
    }

    // ---- epilogue: + bias, scatter rows to out (slot 0) / scr1 (slot 1) ----
    const int quad = lane >> 2, tq = lane & 3;
    #pragma unroll
    for (int mf = 0; mf < 2; mf++) {
        #pragma unroll
        for (int half = 0; half < 2; half++) {
            const int mrow = wm * 32 + mf * 16 + half * 8 + quad;
            const int sv = rowid[mrow];
            if (sv < 0) continue;
            float* dst = ((sv & 1) ? g_scr1 : out) + (size_t)(sv >> 1) * D_MODEL;
            #pragma unroll
            for (int n8 = 0; n8 < 8; n8++) {
                const int gcol = ntile * BN + wn * 64 + n8 * 8 + tq * 2;
                const float* bp = bias + e * D_MODEL + gcol;
                float2 o;
                o.x = acc[mf][n8][half * 2 + 0] + bp[0];
                o.y = acc[mf][n8][half * 2 + 1] + bp[1];
                *reinterpret_cast<float2*>(dst + gcol) = o;
            }
        }
    }
}

// ---------------- kernel: combine (out[t] += scr1[t]) -------------------------
__global__ void combine_kernel(float* __restrict__ out) {
    const long long n4 = (long long)T_TOKENS * D_MODEL / 4;
    const float4* s4 = reinterpret_cast<const float4*>(g_scr1);
    float4* o4 = reinterpret_cast<float4*>(out);
    for (long long i = (long long)blockIdx.x * blockDim.x + threadIdx.x; i < n4;
         i += (long long)gridDim.x * blockDim.x) {
        float4 a = o4[i];
        float4 b = s4[i];
        o4[i] = make_float4(a.x + b.x, a.y + b.y, a.z + b.z, a.w + b.w);
    }
}

// ---------------- launch ------------------------------------------------------
extern "C" void kernel_launch(void* const* d_in, const int* in_sizes, int n_in,
                              void* d_out, int out_size) {
    const float* h  = (const float*)d_in[0];   // [16384, 2048]
    const float* Wg = (const float*)d_in[1];   // [8, 2048]
    const float* bg = (const float*)d_in[2];   // [8]
    const float* W  = (const float*)d_in[3];   // [8, 2048, 2048]
    const float* b  = (const float*)d_in[4];   // [8, 2048]
    float* out = (float*)d_out;                // [16384, 2048]
    (void)in_sizes; (void)n_in; (void)out_size;

    init_kernel<<<1, 32>>>();

    prep_kernel<<<T_TOKENS / 4, 256>>>(h, Wg, bg);                 // h fp16 + router
    convert_w_kernel<<<8192, 256>>>(W, (long long)N_EXP * D_MODEL * D_MODEL / 4);

    cudaFuncSetAttribute(moe_mma_gemm, cudaFuncAttributeMaxDynamicSharedMemorySize, SMEM_TOTAL);
    dim3 grid(NT, N_EXP * (T_TOKENS / BM));
    moe_mma_gemm<<<grid, 256, SMEM_TOTAL>>>(b, out);

    combine_kernel<<<1024, 256>>>(out);
}